// round 17
// baseline (speedup 1.0000x reference)
#include <cuda_runtime.h>

#define BATCH 131072
#define NCH 16
#define NK 15
#define NZ 256
#define NCOUT 10
#define MAXREG 128
#define VOCAB 1024

typedef unsigned long long u64;

// ---------------- scratch (device globals; no allocation) ----------------
__device__ unsigned       g_seen[NCH][1024];     // built by k_masks, read+zeroed by k_tc tables blocks
__device__ unsigned char  g_rmap[NCH][32768];    // mask -> region id (observed entries valid this launch)
__device__ unsigned       g_maskw[BATCH * 8];    // packed masks: channel pair per u32
__device__ int            g_cnt[NCH];            // #distinct masks per channel (<=121)
__device__ float          g_zreg[NCH][MAXREG][NZ];       // per-region half z-row
__device__ unsigned char  g_cross[8][MAXREG][MAXREG];    // argmax index per (c8, rA, rB)
__device__ volatile int   g_flag[NCH];           // per-channel tables-done; reset by k_main

// ================= K1: sign masks — 1 elem/thread, phase-split filter, FULL residency ===
// 131072 threads (256 blocks x 512 thr, all resident at 2 blocks/SM) -> ~886 thr/SM,
// 2x the warps of the 2-elem variant, same cheap packed-constant body.
// Phase A: pairs 0-3 (channels 0-7) with 32 KB filter; sync; clear; Phase B: pairs 4-7.
#define K1_BLK 256
#define K1_THR 512
#define K1_SMEM (8192 + 8192 + 1920 + 960 + 32768)   // 52032 B -> 2 blocks/SM (thread-capped)

__global__ void __launch_bounds__(K1_THR, 2) k_masks(
    const int* __restrict__ x, const float* __restrict__ lenLUT,
    const float* __restrict__ ipdLUT, const float* __restrict__ S,
    const float* __restrict__ T)
{
    extern __shared__ char dyn[];
    float2*     sLen = (float2*)dyn;                     // 8 KB
    float2*     sIpd = (float2*)(dyn + 8192);            // 8 KB
    ulonglong2* sSP  = (ulonglong2*)(dyn + 16384);       // 120 x {S0p, S1p}  (1920 B)
    u64*        sC   = (u64*)(dyn + 16384 + 1920);       // 120 x packed (-T-1e-4) (960 B)
    unsigned*   filt = (unsigned*)(dyn + 16384 + 2880);  // 32 KB filter for 8 channels/phase

    const int tid = threadIdx.x;
    for (int i = tid; i < VOCAB; i += K1_THR) {
        sLen[i] = ((const float2*)lenLUT)[i];
        sIpd[i] = ((const float2*)ipdLUT)[i];
    }
    if (tid < 120) {                                     // pack per-pair plane constants
        int i = tid / NK, k = tid % NK;
        int cA = 2 * i, cB = 2 * i + 1;
        u64 s0 = ((u64)__float_as_uint(S[cB * 30 + k])      << 32) | __float_as_uint(S[cA * 30 + k]);
        u64 s1 = ((u64)__float_as_uint(S[cB * 30 + 15 + k]) << 32) | __float_as_uint(S[cA * 30 + 15 + k]);
        float cAv = -T[cA * NK + k] - 1e-4f;
        float cBv = -T[cB * NK + k] - 1e-4f;
        sSP[tid] = make_ulonglong2(s0, s1);
        sC[tid]  = ((u64)__float_as_uint(cBv) << 32) | __float_as_uint(cAv);
    }
    for (int i = tid; i < 8 * 1024; i += K1_THR) filt[i] = 0u;
    __syncthreads();

    const int b = blockIdx.x * K1_THR + tid;             // exact cover: 256*512 = BATCH
    const int4* xp = (const int4*)x + (size_t)b * 8;
    uint4* mp = (uint4*)&g_maskw[(size_t)b * 8];

    #pragma unroll
    for (int phase = 0; phase < 2; phase++) {
        unsigned w[4];
        #pragma unroll
        for (int ii = 0; ii < 4; ii++) {
            const int i = phase * 4 + ii;                // pair index 0..7
            int4 xv = __ldg(&xp[i]);

            float2 lA = sLen[xv.x], pA = sIpd[xv.y];
            float2 lB = sLen[xv.z], pB = sIpd[xv.w];

            u64 e0p, e1p;
            {
                float a = lA.x + pA.x, b2 = lB.x + pB.x;
                asm("mov.b64 %0, {%1, %2};" : "=l"(e0p) : "f"(a), "f"(b2));
                float c = lA.y + pA.y, d = lB.y + pB.y;
                asm("mov.b64 %0, {%1, %2};" : "=l"(e1p) : "f"(c), "f"(d));
            }

            unsigned pair = 0;
            #pragma unroll
            for (int k = 0; k < NK; k++) {
                ulonglong2 sp = sSP[i * NK + k];         // LDS.128: S0p, S1p
                u64        cc = sC[i * NK + k];          // LDS.64
                u64 t2, y2;
                asm("fma.rn.f32x2 %0, %1, %2, %3;" : "=l"(t2) : "l"(e0p), "l"(sp.x), "l"(cc));
                asm("fma.rn.f32x2 %0, %1, %2, %3;" : "=l"(y2) : "l"(e1p), "l"(sp.y), "l"(t2));
                unsigned lo = (unsigned)y2;
                unsigned hi = (unsigned)(y2 >> 32);
                pair |= ((lo >> 31) << k) | ((hi >> 31) << (16 + k));   // bit set <=> y<0
            }
            w[ii] = pair;

            // inline observation (block filter, this phase's 8 channels -> rare global atomic)
            #pragma unroll
            for (int h2 = 0; h2 < 2; h2++) {
                unsigned m = (pair >> (16 * h2)) & 0xffffu;
                const int c  = 2 * i + h2;               // global channel
                const int cl = c - phase * 8;            // filter-local channel 0..7
                unsigned wd = cl * 1024 + (m >> 5), bt = 1u << (m & 31);
                if (!(filt[wd] & bt)) {
                    unsigned old = atomicOr(&filt[wd], bt);
                    if (!(old & bt)) atomicOr((unsigned*)&g_seen[c][m >> 5], bt);
                }
            }
        }
        mp[phase] = make_uint4(w[0], w[1], w[2], w[3]);

        if (phase == 0) {                                // clear filter for channels 8-15
            __syncthreads();
            for (int i = tid; i < 8 * 1024; i += K1_THR) filt[i] = 0u;
            __syncthreads();
        }
    }
}

// ================= K2: fused tables + cross (unchanged) =================
__global__ void __launch_bounds__(1024, 2) k_tc(const float* __restrict__ H) {  // <<<272, 1024>>>
    const int tid = threadIdx.x;

    __shared__ union {
        struct {                                   // tables path
            int            sc[256];
            unsigned short sMask[MAXREG];
            float          sH[NK][NZ];
            int            s_cnt;
        } t;
        struct {                                   // cross path
            float zA[4][NZ];
        } x;
    } sh;

    if (blockIdx.x < NCH) {
        const int c = blockIdx.x;
        unsigned w[4]; int pc = 0;
        if (tid < 256) {
            #pragma unroll
            for (int j = 0; j < 4; j++) {
                w[j] = g_seen[c][tid * 4 + j];
                g_seen[c][tid * 4 + j] = 0u;               // self-clean for next launch
                pc += __popc(w[j]);
            }
            sh.t.sc[tid] = pc;
        }
        const int base = (c & 1) * NK;                     // even ch -> H rows 0..14, odd -> 15..29
        for (int i = tid; i < NK * NZ; i += 1024)
            sh.t.sH[i >> 8][i & 255] = H[(base + (i >> 8)) * NZ + (i & 255)];
        __syncthreads();
        for (int off = 1; off < 256; off <<= 1) {          // Hillis-Steele inclusive scan
            int v = 0;
            if (tid < 256 && tid >= off) v = sh.t.sc[tid - off];
            __syncthreads();
            if (tid < 256) sh.t.sc[tid] += v;
            __syncthreads();
        }
        if (tid < 256) {
            int id = sh.t.sc[tid] - pc;                    // exclusive prefix (ascending-mask order)
            if (tid == 255) { g_cnt[c] = min(sh.t.sc[255], MAXREG); sh.t.s_cnt = min(sh.t.sc[255], MAXREG); }
            #pragma unroll
            for (int j = 0; j < 4; j++) {
                const int word = tid * 4 + j;
                unsigned ww = w[j];
                const unsigned mb = (unsigned)word << 5;
                while (ww) {
                    int bb = __ffs(ww) - 1; ww &= ww - 1;
                    if (id < MAXREG) {
                        unsigned short mask = (unsigned short)(mb | (unsigned)bb);
                        g_rmap[c][mask] = (unsigned char)id;
                        sh.t.sMask[id] = mask;
                    }
                    id++;
                }
            }
        }
        __syncthreads();

        const int cnt = sh.t.s_cnt;
        const int col = tid & 255, grp = tid >> 8;         // 4-way row parallelism
        for (int r = grp; r < cnt; r += 4) {
            unsigned m = sh.t.sMask[r];
            float acc = 0.f;
            #pragma unroll
            for (int d = 0; d < NK; d++) {
                float hv = sh.t.sH[d][col];
                acc += ((m >> d) & 1) ? -hv : hv;
            }
            g_zreg[c][r][col] = acc;
        }

        __syncthreads();
        __threadfence();
        if (tid == 0) g_flag[c] = 1;
    } else {
        const int idx2 = blockIdx.x - NCH;                 // 0..255
        const int rAt = idx2 & 31;                         // 32 rA tiles of 4
        const int c8  = idx2 >> 5;                         // 8 pairs
        const int cA = 2 * c8, cB = cA + 1;

        if (tid == 0) {                                    // wait for this pair's tables blocks
            while (!(g_flag[cA] && g_flag[cB])) __nanosleep(64);
        }
        __syncthreads();                                   // acquire for the whole block

        const int nA = g_cnt[cA], nB = g_cnt[cB];
        const int rA0 = rAt * 4;
        if (rA0 >= nA) return;
        const int na = min(4, nA - rA0);
        for (int i = tid; i < 4 * NZ; i += 1024) {
            int rr = i >> 8, k = i & 255;
            sh.x.zA[rr][k] = (rr < na) ? g_zreg[cA][rA0 + rr][k] : 0.f;
        }
        __syncthreads();
        const int warp = tid >> 5, lane = tid & 31;        // 32 warps over rB
        for (int rB = warp; rB < nB; rB += 32) {
            const float* zb = &g_zreg[cB][rB][0];
            float zl[8];
            #pragma unroll
            for (int j = 0; j < 8; j++) zl[j] = zb[j * 32 + lane];
            #pragma unroll
            for (int i2 = 0; i2 < 4; i2++) {
                float best = __int_as_float(0xff800000);   // -inf
                int   bk = 0;
                #pragma unroll
                for (int j = 0; j < 8; j++) {
                    int k = j * 32 + lane;                 // ascending per lane
                    float v = sh.x.zA[i2][k] + zl[j];
                    if (v > best) { best = v; bk = k; }
                }
                #pragma unroll
                for (int off = 16; off; off >>= 1) {       // first-index-wins warp argmax
                    float ov = __shfl_down_sync(0xffffffffu, best, off);
                    int   ok = __shfl_down_sync(0xffffffffu, bk, off);
                    if (ov > best || (ov == best && ok < bk)) { best = ov; bk = ok; }
                }
                if (lane == 0 && i2 < na) g_cross[c8][rA0 + i2][rB] = (unsigned char)bk;
            }
        }
    }
}

// ================= K3: gather + log_softmax — 2 elements/thread (unchanged) =============
#define K4_BLK 256
#define K4_THR 256
#define LUTPAD 12
#define K4_SMEM (8 * 256 * LUTPAD * 4)   // 98304 B -> 2 blocks/SM

__global__ void __launch_bounds__(K4_THR, 2) k_main(
    const float* __restrict__ LUT, float* __restrict__ out)
{
    extern __shared__ char dyn[];
    float* slut = (float*)dyn;

    const int tid = threadIdx.x;
    if (blockIdx.x == 0 && tid < NCH) g_flag[tid] = 0;   // reset flags for next launch
    for (int row = tid; row < 8 * 256; row += K4_THR) {
        #pragma unroll
        for (int j = 0; j < LUTPAD; j++)
            slut[row * LUTPAD + j] = (j < NCOUT) ? LUT[row * NCOUT + j] : 0.f;
    }
    __syncthreads();

    const int b0 = blockIdx.x * K4_THR + tid;            // 65536 threads, 2 elems each
    const int b1 = b0 + 65536;

    const uint4* mp0 = (const uint4*)&g_maskw[(size_t)b0 * 8];
    const uint4* mp1 = (const uint4*)&g_maskw[(size_t)b1 * 8];
    uint4 a0v = mp0[0], a1v = mp0[1], b0v = mp1[0], b1v = mp1[1];
    unsigned mwA[8] = {a0v.x, a0v.y, a0v.z, a0v.w, a1v.x, a1v.y, a1v.z, a1v.w};
    unsigned mwB[8] = {b0v.x, b0v.y, b0v.z, b0v.w, b1v.x, b1v.y, b1v.z, b1v.w};

    int rA[NCH], rB[NCH];
    #pragma unroll
    for (int i = 0; i < 8; i++) {                        // 32 independent rmap u8 loads
        rA[2 * i]     = __ldg(&g_rmap[2 * i][mwA[i] & 0xffffu]);
        rA[2 * i + 1] = __ldg(&g_rmap[2 * i + 1][mwA[i] >> 16]);
        rB[2 * i]     = __ldg(&g_rmap[2 * i][mwB[i] & 0xffffu]);
        rB[2 * i + 1] = __ldg(&g_rmap[2 * i + 1][mwB[i] >> 16]);
    }

    int idxA[8], idxB[8];
    #pragma unroll
    for (int c8 = 0; c8 < 8; c8++) {                     // 16 independent cross u8 loads
        idxA[c8] = __ldg(&g_cross[c8][rA[2 * c8]][rA[2 * c8 + 1]]);
        idxB[c8] = __ldg(&g_cross[c8][rB[2 * c8]][rB[2 * c8 + 1]]);
    }

    #pragma unroll
    for (int e = 0; e < 2; e++) {
        const int* idx = e ? idxB : idxA;
        const int  b   = e ? b1 : b0;

        float4 q0 = make_float4(0.f, 0.f, 0.f, 0.f), q1 = q0, q2 = q0;
        #pragma unroll
        for (int c8 = 0; c8 < 8; c8++) {
            const float4* p = (const float4*)&slut[(c8 * 256 + idx[c8]) * LUTPAD];
            float4 v0 = p[0], v1 = p[1], v2 = p[2];
            q0.x += v0.x; q0.y += v0.y; q0.z += v0.z; q0.w += v0.w;
            q1.x += v1.x; q1.y += v1.y; q1.z += v1.z; q1.w += v1.w;
            q2.x += v2.x; q2.y += v2.y;                  // lanes 10,11 are pad
        }
        float acc[NCOUT] = {q0.x, q0.y, q0.z, q0.w, q1.x, q1.y, q1.z, q1.w, q2.x, q2.y};

        float mx = acc[0];
        #pragma unroll
        for (int j = 1; j < NCOUT; j++) mx = fmaxf(mx, acc[j]);
        float s = 0.f;
        #pragma unroll
        for (int j = 0; j < NCOUT; j++) s += __expf(acc[j] - mx);
        float lg = __logf(s);

        float2* op = (float2*)(out + (size_t)b * NCOUT);
        #pragma unroll
        for (int j = 0; j < 5; j++)
            op[j] = make_float2((acc[2 * j] - mx) - lg, (acc[2 * j + 1] - mx) - lg);
    }
}

// ---------------- launch ----------------
extern "C" void kernel_launch(void* const* d_in, const int* in_sizes, int n_in,
                              void* d_out, int out_size) {
    const int*   x      = (const int*)d_in[0];
    const float* lenLUT = (const float*)d_in[1];
    const float* ipdLUT = (const float*)d_in[2];
    const float* S      = (const float*)d_in[3];
    const float* H      = (const float*)d_in[4];
    const float* T      = (const float*)d_in[5];
    const float* LUT    = (const float*)d_in[6];
    float*       out    = (float*)d_out;

    static int attr_done = 0;   // host-side, idempotent (set on the pre-capture correctness call)
    if (!attr_done) {
        cudaFuncSetAttribute(k_masks, cudaFuncAttributeMaxDynamicSharedMemorySize, K1_SMEM);
        cudaFuncSetAttribute(k_main,  cudaFuncAttributeMaxDynamicSharedMemorySize, K4_SMEM);
        attr_done = 1;
    }

    k_masks<<<K1_BLK, K1_THR, K1_SMEM>>>(x, lenLUT, ipdLUT, S, T);
    k_tc   <<<NCH + 256, 1024>>>(H);
    k_main <<<K4_BLK, K4_THR, K4_SMEM>>>(LUT, out);
}